// round 12
// baseline (speedup 1.0000x reference)
#include <cuda_runtime.h>
#include <cstdint>

// L1Attn: out[b,i,j,h] = -(1/8) * sum_d |q[b,j,h,d] - k[b,i,h,d]|
// B=8, S=1024, H=8, D=64. Output [B,S,S,H] (i = keys, j = queries).
//
// Double-buffered cp.async pipeline: q staged in 8-d chunks into 2 buffers;
// stage(c+1) issued BEFORE computing chunk c, wait_group 1 hides LDG latency
// behind a full chunk of compute. Block = 8 i x 64 j x 8 h (3 blocks/SM);
// thread = one h, 8 i x 2 j outputs, d-pair packed f32x2 math.

namespace {
constexpr int S  = 1024;
constexpr int H  = 8;
constexpr int D  = 64;
constexpr int NT = 256;
constexpr int TI = 8;      // i per block
constexpr int JB = 64;     // j per block: 32 (w,jl) slots x 2 u
constexpr int NU = 2;      // j outputs per thread
constexpr int CD = 8;      // d per q chunk
constexpr int NC = D / CD;           // 8 chunks
constexpr int KROW = 68;             // k row: 64 d + 4 pad (h-rows on distinct quads)
constexpr int QROW = 12;             // q row: 8 d + 4 pad (3*row mod 8 covers quads)
constexpr int QR   = JB * H;         // 512 q rows per chunk buffer
constexpr int KS_FLOATS = TI * H * KROW;   // 4352  (17408 B)
constexpr int QS_FLOATS = QR * QROW;       // 6144  (24576 B) per buffer
constexpr unsigned SMEM_BYTES = (KS_FLOATS + 2 * QS_FLOATS) * 4;  // 66560
static_assert(S % JB == 0, "JB must divide S");

typedef unsigned long long ull;

__device__ __forceinline__ ull subx2(ull a, ull b) {
    ull r;
    asm("sub.rn.f32x2 %0, %1, %2;" : "=l"(r) : "l"(a), "l"(b));
    return r;
}
__device__ __forceinline__ ull addx2(ull a, ull b) {
    ull r;
    asm("add.rn.f32x2 %0, %1, %2;" : "=l"(r) : "l"(a), "l"(b));
    return r;
}
__device__ __forceinline__ void cp16(uint32_t dst_smem, const float* src) {
    asm volatile("cp.async.cg.shared.global [%0], [%1], 16;"
                 :: "r"(dst_smem), "l"(src));
}
}  // namespace

__global__ void __launch_bounds__(NT, 3) l1attn_kernel(
    const float* __restrict__ qg,
    const float* __restrict__ kg,
    float* __restrict__ out)
{
    extern __shared__ __align__(16) float smf[];
    float* ks = smf;                          // [64 rows][68]
    float* qb0 = smf + KS_FLOATS;
    float* qb1 = qb0 + QS_FLOATS;

    const int t  = threadIdx.x;
    const int j0 = blockIdx.x * JB;
    const int i0 = blockIdx.y * TI;
    const int b  = blockIdx.z;

    const float* qtile = qg + ((size_t)b * S + j0) * (size_t)(H * D);
    const uint32_t qsb0 = (uint32_t)__cvta_generic_to_shared(qb0);
    const uint32_t qsb1 = (uint32_t)__cvta_generic_to_shared(qb1);

    // ---- Prologue: issue q chunk 0 into buffer 0 ----
    #pragma unroll
    for (int r = 0; r < (QR * CD) / (4 * NT); r++) {   // 4 iters
        int p   = t + r * NT;      // float4 piece 0..1023
        int row = p >> 1;          // 0..511
        int sg  = p & 1;
        cp16(qsb0 + (row * QROW + sg * 4) * 4, qtile + row * D + sg * 4);
    }
    asm volatile("cp.async.commit_group;" ::: "memory");

    // ---- Stage k tile: rows (ii*8 + h), 64 floats each ----
    {
        const float* kb = kg + ((size_t)b * S + i0) * (size_t)(H * D);
        #pragma unroll
        for (int r = 0; r < (TI * H * D) / (4 * NT); r++) {  // 4 iters
            int idx = t + r * NT;
            int row = idx >> 4;
            int dd  = (idx & 15) << 2;
            float4 v = *reinterpret_cast<const float4*>(kb + row * D + dd);
            *reinterpret_cast<float4*>(&ks[row * KROW + dd]) = v;
        }
    }

    const int h  = t & 7;
    const int jl = (t >> 3) & 3;
    const int w  = t >> 5;
    const int slot = w * 4 + jl;            // 0..31
    const int jbase = j0 + slot;            // u adds 32 j
    const int qrow0 = slot * 8 + h;         // u adds 32 j = 256 rows (max 767 < 512*... )

    const ull MSK = 0x7FFFFFFF7FFFFFFFULL;

    ull acc[TI][NU];
    #pragma unroll
    for (int i = 0; i < TI; i++)
        #pragma unroll
        for (int u = 0; u < NU; u++) acc[i][u] = 0ULL;

    #pragma unroll 1
    for (int cc = 0; cc < NC; cc++) {
        // ---- Issue stage(cc+1) into the other buffer, then wait for cc ----
        if (cc + 1 < NC) {
            const float* qc = qtile + (cc + 1) * CD;
            uint32_t dstb = ((cc + 1) & 1) ? qsb1 : qsb0;
            #pragma unroll
            for (int r = 0; r < (QR * CD) / (4 * NT); r++) {
                int p   = t + r * NT;
                int row = p >> 1;
                int sg  = p & 1;
                cp16(dstb + (row * QROW + sg * 4) * 4, qc + row * D + sg * 4);
            }
            asm volatile("cp.async.commit_group;" ::: "memory");
            asm volatile("cp.async.wait_group 1;" ::: "memory");  // stage(cc) done
        } else {
            asm volatile("cp.async.wait_group 0;" ::: "memory");
        }
        __syncthreads();   // stage(cc) visible to all threads

        // ---- Compute on chunk cc: 2 steps of 4 d ----
        const float* qs = (cc & 1) ? qb1 : qb0;
        #pragma unroll
        for (int s = 0; s < 2; s++) {
            ull qv[NU][2];
            #pragma unroll
            for (int u = 0; u < NU; u++) {
                ulonglong2 q2 = *reinterpret_cast<const ulonglong2*>(
                    qs + (qrow0 + u * 256) * QROW + s * 4);
                qv[u][0] = q2.x;
                qv[u][1] = q2.y;
            }
            const float* kr = ks + h * KROW + cc * CD + s * 4;
            #pragma unroll
            for (int i = 0; i < TI; i++) {
                ulonglong2 kv = *reinterpret_cast<const ulonglong2*>(kr + i * (8 * KROW));
                #pragma unroll
                for (int u = 0; u < NU; u++) {
                    ull t0 = subx2(kv.x, qv[u][0]) & MSK;   // |k-q| d pair 0
                    ull t1 = subx2(kv.y, qv[u][1]) & MSK;   // d pair 1
                    acc[i][u] = addx2(acc[i][u], addx2(t0, t1));
                }
            }
        }
        __syncthreads();   // reads of buf[cc&1] done before stage(cc+2) overwrites
    }

    // ---- Epilogue: reduce packed halves, scale, coalesced stores ----
    const float scale = -0.125f;  // -1/sqrt(64)
    #pragma unroll
    for (int i = 0; i < TI; i++) {
        const size_t ob = (((size_t)b * S + (i0 + i)) * S + jbase) * H + h;
        #pragma unroll
        for (int u = 0; u < NU; u++) {
            unsigned int lo = (unsigned int)(acc[i][u] & 0xffffffffu);
            unsigned int hi = (unsigned int)(acc[i][u] >> 32);
            out[ob + (size_t)u * (32 * H)] =
                (__uint_as_float(lo) + __uint_as_float(hi)) * scale;
        }
    }
}

extern "C" void kernel_launch(void* const* d_in, const int* in_sizes, int n_in,
                              void* d_out, int out_size) {
    const float* q = (const float*)d_in[0];
    const float* k = (const float*)d_in[1];
    float* out     = (float*)d_out;

    cudaFuncSetAttribute(l1attn_kernel,
                         cudaFuncAttributeMaxDynamicSharedMemorySize, SMEM_BYTES);

    const int B = in_sizes[0] / (S * H * D);  // = 8
    dim3 grid(S / JB, S / TI, B);
    l1attn_kernel<<<grid, NT, SMEM_BYTES>>>(q, k, out);
}

// round 13
// speedup vs baseline: 1.8220x; 1.8220x over previous
#include <cuda_runtime.h>
#include <cuda_fp16.h>
#include <cstdint>

// L1Attn: out[b,i,j,h] = -(1/8) * sum_d |q[b,j,h,d] - k[b,i,h,d]|
// B=8, S=1024, H=8, D=64. Output [B,S,S,H] (i = keys, j = queries).
//
// fp16x2 math: inputs converted once to fp16 during staging; HSUB2 +
// HABS2 + HADD2 replace subx2 + 2xLOP3 + addx2 (abs is a sign-bit op in
// fp16, foldable). Partial fp16 accumulation over 16 d, merged into fp32
// (norm rel-err ~2.4e-4 << 1e-3). Full-D tiles staged once (no chunk
// barriers). Block = 8 i x 64 j x 8 h; thread = one h, 8 i x 2 j outputs.

namespace {
constexpr int S  = 1024;
constexpr int H  = 8;
constexpr int D  = 64;
constexpr int NT = 256;
constexpr int TI = 8;      // i per block
constexpr int JB = 64;     // j per block: 32 (w,jl) slots x 2 u
constexpr int NU = 2;      // j outputs per thread
constexpr int ROWH = 68;   // halfs per row: 64 d + 4 pad (136 B -> uniform 2/bank)
constexpr int QR  = JB * H;            // 512 q rows
constexpr int KR  = TI * H;            // 64 k rows
constexpr int QS_HALF = QR * ROWH;     // 34816 halfs (69632 B)
constexpr int KS_HALF = KR * ROWH;     // 4352  halfs (8704 B)
constexpr unsigned SMEM_BYTES = (QS_HALF + KS_HALF) * 2;  // 78336
static_assert(S % JB == 0, "JB must divide S");

struct __align__(8) H4 { __half2 a, b; };   // 4 halfs = 8 B
struct __align__(16) H8 { __half2 a, b, c, d; };  // 8 halfs = 16 B
}  // namespace

__global__ void __launch_bounds__(NT, 2) l1attn_kernel(
    const float* __restrict__ qg,
    const float* __restrict__ kg,
    float* __restrict__ out)
{
    extern __shared__ __align__(16) __half smh[];
    __half* ksm = smh;              // k: [64 rows][68]
    __half* qsm = smh + KS_HALF;    // q: [512 rows][68], row = jj*8 + h

    const int t  = threadIdx.x;
    const int j0 = blockIdx.x * JB;
    const int i0 = blockIdx.y * TI;
    const int b  = blockIdx.z;

    // ---- Stage k (convert fp32 -> fp16): 64 rows x 64 d ----
    {
        const float* kb = kg + ((size_t)b * S + i0) * (size_t)(H * D);
        #pragma unroll
        for (int r = 0; r < (KR * D) / (4 * NT); r++) {   // 4 iters
            int p   = t + r * NT;       // float4 piece
            int row = p >> 4;
            int dg  = p & 15;
            float4 v = *reinterpret_cast<const float4*>(kb + row * D + dg * 4);
            H4 hv;
            hv.a = __floats2half2_rn(v.x, v.y);
            hv.b = __floats2half2_rn(v.z, v.w);
            *reinterpret_cast<H4*>(ksm + row * ROWH + dg * 4) = hv;
        }
    }
    // ---- Stage q (convert fp32 -> fp16): 512 rows x 64 d ----
    {
        const float* qt = qg + ((size_t)b * S + j0) * (size_t)(H * D);
        #pragma unroll
        for (int r = 0; r < (QR * D) / (4 * NT); r++) {   // 32 iters
            int p   = t + r * NT;
            int row = p >> 4;
            int dg  = p & 15;
            float4 v = *reinterpret_cast<const float4*>(qt + row * D + dg * 4);
            H4 hv;
            hv.a = __floats2half2_rn(v.x, v.y);
            hv.b = __floats2half2_rn(v.z, v.w);
            *reinterpret_cast<H4*>(qsm + row * ROWH + dg * 4) = hv;
        }
    }
    __syncthreads();

    const int h  = t & 7;
    const int jl = (t >> 3) & 3;
    const int w  = t >> 5;
    const int slot  = w * 4 + jl;        // 0..31
    const int jbase = j0 + slot;         // u adds 32 j
    const int qrow0 = slot * 8 + h;      // u adds 32 j = 256 rows (max 511)

    float f_acc[TI][NU];
    #pragma unroll
    for (int i = 0; i < TI; i++)
        #pragma unroll
        for (int u = 0; u < NU; u++) f_acc[i][u] = 0.0f;

    const __half2 hz = __float2half2_rn(0.0f);

    // 4 partials of 16 d; each partial = 2 steps of 8 d, fp16 accumulation,
    // then merged into fp32 (bounds fp16 rounding error).
    #pragma unroll 1
    for (int pp = 0; pp < 4; pp++) {
        __half2 h_acc[TI][NU];
        #pragma unroll
        for (int i = 0; i < TI; i++)
            #pragma unroll
            for (int u = 0; u < NU; u++) h_acc[i][u] = hz;

        #pragma unroll
        for (int s = 0; s < 2; s++) {
            const int doff = (pp * 2 + s) * 8;   // half offset of this 8-d step
            H8 qv[NU];
            #pragma unroll
            for (int u = 0; u < NU; u++)
                qv[u] = *reinterpret_cast<const H8*>(
                    qsm + (qrow0 + u * 256) * ROWH + doff);
            const __half* kp = ksm + h * ROWH + doff;
            #pragma unroll
            for (int i = 0; i < TI; i++) {
                H8 kv = *reinterpret_cast<const H8*>(kp + i * (8 * ROWH));
                #pragma unroll
                for (int u = 0; u < NU; u++) {
                    h_acc[i][u] = __hadd2(h_acc[i][u], __habs2(__hsub2(kv.a, qv[u].a)));
                    h_acc[i][u] = __hadd2(h_acc[i][u], __habs2(__hsub2(kv.b, qv[u].b)));
                    h_acc[i][u] = __hadd2(h_acc[i][u], __habs2(__hsub2(kv.c, qv[u].c)));
                    h_acc[i][u] = __hadd2(h_acc[i][u], __habs2(__hsub2(kv.d, qv[u].d)));
                }
            }
        }
        // ---- Merge partial into fp32 ----
        #pragma unroll
        for (int i = 0; i < TI; i++)
            #pragma unroll
            for (int u = 0; u < NU; u++) {
                float2 f2 = __half22float2(h_acc[i][u]);
                f_acc[i][u] += f2.x + f2.y;
            }
    }

    // ---- Epilogue: scale, coalesced stores ----
    const float scale = -0.125f;  // -1/sqrt(64)
    #pragma unroll
    for (int i = 0; i < TI; i++) {
        const size_t ob = (((size_t)b * S + (i0 + i)) * S + jbase) * H + h;
        #pragma unroll
        for (int u = 0; u < NU; u++)
            out[ob + (size_t)u * (32 * H)] = f_acc[i][u] * scale;
    }
}

extern "C" void kernel_launch(void* const* d_in, const int* in_sizes, int n_in,
                              void* d_out, int out_size) {
    const float* q = (const float*)d_in[0];
    const float* k = (const float*)d_in[1];
    float* out     = (float*)d_out;

    cudaFuncSetAttribute(l1attn_kernel,
                         cudaFuncAttributeMaxDynamicSharedMemorySize, SMEM_BYTES);

    const int B = in_sizes[0] / (S * H * D);  // = 8
    dim3 grid(S / JB, S / TI, B);
    l1attn_kernel<<<grid, NT, SMEM_BYTES>>>(q, k, out);
}

// round 14
// speedup vs baseline: 2.0162x; 1.1066x over previous
#include <cuda_runtime.h>
#include <cuda_fp16.h>
#include <cstdint>

// L1Attn: out[b,i,j,h] = -(1/8) * sum_d |q[b,j,h,d] - k[b,i,h,d]|
// B=8, S=1024, H=8, D=64. Output [B,S,S,H] (i = keys, j = queries).
//
// Two-kernel scheme:
//  1) convert_kernel: fp32 -> fp16 once into __device__ scratch (~12 us).
//  2) l1attn_kernel: fp16x2 HSUB2/HADD2 (abs folded) mainloop.
//     ROWH=72 (144 B rows) -> LDS.128 phases hit banks 0..31 exactly once
//     (conflict-free; ROWH=68 had 2-way conflicts = the 70% L1 in R13).
//     q/k staged via cp.async (no per-block conversion); fp16 partials over
//     32 d, tree-summed, merged to fp32 twice (rel_err ~3e-4 < 1e-3).

namespace {
constexpr int S  = 1024;
constexpr int H  = 8;
constexpr int D  = 64;
constexpr int NT = 256;
constexpr int TI = 8;      // i per block
constexpr int JB = 64;     // j per block: 32 (w,jl) slots x 2 u
constexpr int NU = 2;      // j outputs per thread
constexpr int ROWH = 72;   // halfs per row: 64 d + 8 pad (144 B: +4 banks/row)
constexpr int QR  = JB * H;            // 512 q rows
constexpr int KR  = TI * H;            // 64 k rows
constexpr int QS_HALF = QR * ROWH;     // 36864 halfs (73728 B)
constexpr int KS_HALF = KR * ROWH;     // 4608  halfs (9216 B)
constexpr unsigned SMEM_BYTES = (QS_HALF + KS_HALF) * 2;  // 82944
constexpr int NELEM = 8 * S * H * D;   // 4M per tensor (B=8)
static_assert(S % JB == 0, "JB must divide S");

struct __align__(8)  H4 { __half2 a, b; };
struct __align__(16) H8 { __half2 a, b, c, d; };
}  // namespace

__device__ __half qh_g[NELEM];
__device__ __half kh_g[NELEM];

__global__ void convert_kernel(const float* __restrict__ q,
                               const float* __restrict__ k, int n4) {
    int idx = blockIdx.x * blockDim.x + threadIdx.x;
    if (idx >= n4) return;
    float4 qv = reinterpret_cast<const float4*>(q)[idx];
    float4 kv = reinterpret_cast<const float4*>(k)[idx];
    H4 qh, kh;
    qh.a = __floats2half2_rn(qv.x, qv.y);
    qh.b = __floats2half2_rn(qv.z, qv.w);
    kh.a = __floats2half2_rn(kv.x, kv.y);
    kh.b = __floats2half2_rn(kv.z, kv.w);
    reinterpret_cast<H4*>(qh_g)[idx] = qh;
    reinterpret_cast<H4*>(kh_g)[idx] = kh;
}

__device__ __forceinline__ void cp16(uint32_t dst_smem, const __half* src) {
    asm volatile("cp.async.cg.shared.global [%0], [%1], 16;"
                 :: "r"(dst_smem), "l"(src));
}

__global__ void __launch_bounds__(NT, 2) l1attn_kernel(float* __restrict__ out)
{
    extern __shared__ __align__(16) __half smh[];
    __half* ksm = smh;              // k: [64 rows][72]
    __half* qsm = smh + KS_HALF;    // q: [512 rows][72], row = jj*8 + h

    const int t  = threadIdx.x;
    const int j0 = blockIdx.x * JB;
    const int i0 = blockIdx.y * TI;
    const int b  = blockIdx.z;

    const uint32_t ksb = (uint32_t)__cvta_generic_to_shared(ksm);
    const uint32_t qsb = (uint32_t)__cvta_generic_to_shared(qsm);

    // ---- Stage k: 64 rows x 64 halfs (8 x 16B segs per row) ----
    {
        const __half* kb = kh_g + ((size_t)b * S + i0) * (size_t)(H * D);
        #pragma unroll
        for (int r = 0; r < (KR * 8) / NT; r++) {      // 2 iters
            int p   = t + r * NT;     // seg piece 0..511
            int row = p >> 3;
            int sg  = p & 7;
            cp16(ksb + (row * ROWH + sg * 8) * 2, kb + row * D + sg * 8);
        }
    }
    // ---- Stage q: 512 rows x 64 halfs ----
    {
        const __half* qt = qh_g + ((size_t)b * S + j0) * (size_t)(H * D);
        #pragma unroll
        for (int r = 0; r < (QR * 8) / NT; r++) {      // 16 iters
            int p   = t + r * NT;     // seg piece 0..4095
            int row = p >> 3;
            int sg  = p & 7;
            cp16(qsb + (row * ROWH + sg * 8) * 2, qt + row * D + sg * 8);
        }
    }
    asm volatile("cp.async.commit_group;" ::: "memory");
    asm volatile("cp.async.wait_group 0;" ::: "memory");
    __syncthreads();

    const int h  = t & 7;
    const int jl = (t >> 3) & 3;
    const int w  = t >> 5;
    const int slot  = w * 4 + jl;        // 0..31
    const int jbase = j0 + slot;         // u adds 32 j
    const int qrow0 = slot * 8 + h;      // u adds 32 j = 256 rows (max 511)

    float f_acc[TI][NU];
    #pragma unroll
    for (int i = 0; i < TI; i++)
        #pragma unroll
        for (int u = 0; u < NU; u++) f_acc[i][u] = 0.0f;

    const __half2 hz = __float2half2_rn(0.0f);

    // 2 partials of 32 d; each = 4 steps of 8 d, fp16 accumulation (tree),
    // merged into fp32.
    #pragma unroll 1
    for (int pp = 0; pp < 2; pp++) {
        __half2 h_acc[TI][NU];
        #pragma unroll
        for (int i = 0; i < TI; i++)
            #pragma unroll
            for (int u = 0; u < NU; u++) h_acc[i][u] = hz;

        #pragma unroll
        for (int s = 0; s < 4; s++) {
            const int doff = (pp * 4 + s) * 8;   // half offset of this 8-d step
            H8 qv[NU];
            #pragma unroll
            for (int u = 0; u < NU; u++)
                qv[u] = *reinterpret_cast<const H8*>(
                    qsm + (qrow0 + u * 256) * ROWH + doff);
            const __half* kp = ksm + h * ROWH + doff;
            #pragma unroll
            for (int i = 0; i < TI; i++) {
                H8 kv = *reinterpret_cast<const H8*>(kp + i * (8 * ROWH));
                #pragma unroll
                for (int u = 0; u < NU; u++) {
                    __half2 s0 = __hadd2(__habs2(__hsub2(kv.a, qv[u].a)),
                                         __habs2(__hsub2(kv.b, qv[u].b)));
                    __half2 s1 = __hadd2(__habs2(__hsub2(kv.c, qv[u].c)),
                                         __habs2(__hsub2(kv.d, qv[u].d)));
                    h_acc[i][u] = __hadd2(h_acc[i][u], __hadd2(s0, s1));
                }
            }
        }
        // ---- Merge partial into fp32 ----
        #pragma unroll
        for (int i = 0; i < TI; i++)
            #pragma unroll
            for (int u = 0; u < NU; u++) {
                float2 f2 = __half22float2(h_acc[i][u]);
                f_acc[i][u] += f2.x + f2.y;
            }
    }

    // ---- Epilogue: scale, coalesced stores ----
    const float scale = -0.125f;  // -1/sqrt(64)
    #pragma unroll
    for (int i = 0; i < TI; i++) {
        const size_t ob = (((size_t)b * S + (i0 + i)) * S + jbase) * H + h;
        #pragma unroll
        for (int u = 0; u < NU; u++)
            out[ob + (size_t)u * (32 * H)] = f_acc[i][u] * scale;
    }
}

extern "C" void kernel_launch(void* const* d_in, const int* in_sizes, int n_in,
                              void* d_out, int out_size) {
    const float* q = (const float*)d_in[0];
    const float* k = (const float*)d_in[1];
    float* out     = (float*)d_out;

    cudaFuncSetAttribute(l1attn_kernel,
                         cudaFuncAttributeMaxDynamicSharedMemorySize, SMEM_BYTES);

    const int n4 = in_sizes[0] / 4;
    convert_kernel<<<(n4 + NT - 1) / NT, NT>>>(q, k, n4);

    const int B = in_sizes[0] / (S * H * D);  // = 8
    dim3 grid(S / JB, S / TI, B);
    l1attn_kernel<<<grid, NT, SMEM_BYTES>>>(out);
}

// round 15
// speedup vs baseline: 2.2231x; 1.1026x over previous
#include <cuda_runtime.h>
#include <cuda_fp16.h>
#include <cstdint>

// L1Attn: out[b,i,j,h] = -(1/8) * sum_d |q[b,j,h,d] - k[b,i,h,d]|
// B=8, S=1024, H=8, D=64. Output [B,S,S,H] (i = keys, j = queries).
//
// Two kernels: fp32->fp16 convert once; then fp16x2 mainloop.
// Block persists over NI=8 i-tiles with its q tile resident in smem
// (staged once, was re-staged 128x). k tiles (9 KB) double-buffered via
// cp.async, staged during compute -> staging no longer serializes with
// the fma pipe. ROWH=72 keeps LDS conflict-free.

namespace {
constexpr int S  = 1024;
constexpr int H  = 8;
constexpr int D  = 64;
constexpr int NT = 256;
constexpr int TI = 8;      // i per tile
constexpr int NI = 8;      // i-tiles per block
constexpr int JB = 64;     // j per block: 32 (w,jl) slots x 2 u
constexpr int NU = 2;      // j outputs per thread
constexpr int ROWH = 72;   // halfs per row: 64 d + 8 pad (conflict-free)
constexpr int QR  = JB * H;            // 512 q rows
constexpr int KR  = TI * H;            // 64 k rows
constexpr int QS_HALF = QR * ROWH;     // 36864 halfs (73728 B)
constexpr int KS_HALF = KR * ROWH;     // 4608  halfs (9216 B) per buffer
constexpr unsigned SMEM_BYTES = (QS_HALF + 2 * KS_HALF) * 2;  // 92160
constexpr int NELEM = 8 * S * H * D;
static_assert(S % JB == 0 && S % (TI * NI) == 0, "tiling must divide S");

struct __align__(8)  H4 { __half2 a, b; };
struct __align__(16) H8 { __half2 a, b, c, d; };
}  // namespace

__device__ __half qh_g[NELEM];
__device__ __half kh_g[NELEM];

__global__ void convert_kernel(const float* __restrict__ q,
                               const float* __restrict__ k, int n4) {
    int idx = blockIdx.x * blockDim.x + threadIdx.x;
    if (idx >= n4) return;
    float4 qv = reinterpret_cast<const float4*>(q)[idx];
    float4 kv = reinterpret_cast<const float4*>(k)[idx];
    H4 qh, kh;
    qh.a = __floats2half2_rn(qv.x, qv.y);
    qh.b = __floats2half2_rn(qv.z, qv.w);
    kh.a = __floats2half2_rn(kv.x, kv.y);
    kh.b = __floats2half2_rn(kv.z, kv.w);
    reinterpret_cast<H4*>(qh_g)[idx] = qh;
    reinterpret_cast<H4*>(kh_g)[idx] = kh;
}

__device__ __forceinline__ void cp16(uint32_t dst_smem, const __half* src) {
    asm volatile("cp.async.cg.shared.global [%0], [%1], 16;"
                 :: "r"(dst_smem), "l"(src));
}

__global__ void __launch_bounds__(NT, 2) l1attn_kernel(float* __restrict__ out)
{
    extern __shared__ __align__(16) __half smh[];
    __half* qsm  = smh;                       // q: [512 rows][72]
    __half* kbuf0 = smh + QS_HALF;            // k buffers: [64 rows][72] x2
    __half* kbuf1 = kbuf0 + KS_HALF;

    const int t   = threadIdx.x;
    const int j0  = blockIdx.x * JB;
    const int ig0 = blockIdx.y * NI;          // first i-tile index
    const int b   = blockIdx.z;

    const uint32_t qsb  = (uint32_t)__cvta_generic_to_shared(qsm);
    const uint32_t ksb0 = (uint32_t)__cvta_generic_to_shared(kbuf0);
    const uint32_t ksb1 = (uint32_t)__cvta_generic_to_shared(kbuf1);

    // ---- Prologue: stage q tile (once) + k tile 0; one commit group ----
    {
        const __half* qt = qh_g + ((size_t)b * S + j0) * (size_t)(H * D);
        #pragma unroll
        for (int r = 0; r < (QR * 8) / NT; r++) {      // 16 iters
            int p   = t + r * NT;
            int row = p >> 3;
            int sg  = p & 7;
            cp16(qsb + (row * ROWH + sg * 8) * 2, qt + row * D + sg * 8);
        }
        const __half* kb = kh_g + ((size_t)b * S + ig0 * TI) * (size_t)(H * D);
        #pragma unroll
        for (int r = 0; r < (KR * 8) / NT; r++) {      // 2 iters
            int p   = t + r * NT;
            int row = p >> 3;
            int sg  = p & 7;
            cp16(ksb0 + (row * ROWH + sg * 8) * 2, kb + row * D + sg * 8);
        }
        asm volatile("cp.async.commit_group;" ::: "memory");
    }

    const int h  = t & 7;
    const int jl = (t >> 3) & 3;
    const int w  = t >> 5;
    const int slot  = w * 4 + jl;        // 0..31
    const int jbase = j0 + slot;         // u adds 32 j
    const int qrow0 = slot * 8 + h;      // u adds 32 j = 256 rows

    const __half2 hz = __float2half2_rn(0.0f);
    const float scale = -0.125f;  // -1/sqrt(64)

    #pragma unroll 1
    for (int n = 0; n < NI; n++) {
        // ---- Stage k(n+1) into the other buffer, then wait for k(n) ----
        if (n + 1 < NI) {
            const __half* kb = kh_g +
                ((size_t)b * S + (ig0 + n + 1) * TI) * (size_t)(H * D);
            uint32_t dstb = ((n + 1) & 1) ? ksb1 : ksb0;
            #pragma unroll
            for (int r = 0; r < (KR * 8) / NT; r++) {
                int p   = t + r * NT;
                int row = p >> 3;
                int sg  = p & 7;
                cp16(dstb + (row * ROWH + sg * 8) * 2, kb + row * D + sg * 8);
            }
            asm volatile("cp.async.commit_group;" ::: "memory");
            asm volatile("cp.async.wait_group 1;" ::: "memory");
        } else {
            asm volatile("cp.async.wait_group 0;" ::: "memory");
        }
        __syncthreads();   // k(n) (and q on n=0) visible to all

        const __half* ksm = (n & 1) ? kbuf1 : kbuf0;

        float f_acc[TI][NU];
        #pragma unroll
        for (int i = 0; i < TI; i++)
            #pragma unroll
            for (int u = 0; u < NU; u++) f_acc[i][u] = 0.0f;

        // 2 partials of 32 d, fp16 accumulation, merged into fp32.
        #pragma unroll
        for (int pp = 0; pp < 2; pp++) {
            __half2 h_acc[TI][NU];
            #pragma unroll
            for (int i = 0; i < TI; i++)
                #pragma unroll
                for (int u = 0; u < NU; u++) h_acc[i][u] = hz;

            #pragma unroll
            for (int s = 0; s < 4; s++) {
                const int doff = (pp * 4 + s) * 8;
                H8 qv[NU];
                #pragma unroll
                for (int u = 0; u < NU; u++)
                    qv[u] = *reinterpret_cast<const H8*>(
                        qsm + (qrow0 + u * 256) * ROWH + doff);
                const __half* kp = ksm + h * ROWH + doff;
                #pragma unroll
                for (int i = 0; i < TI; i++) {
                    H8 kv = *reinterpret_cast<const H8*>(kp + i * (8 * ROWH));
                    #pragma unroll
                    for (int u = 0; u < NU; u++) {
                        __half2 s0 = __hadd2(__habs2(__hsub2(kv.a, qv[u].a)),
                                             __habs2(__hsub2(kv.b, qv[u].b)));
                        __half2 s1 = __hadd2(__habs2(__hsub2(kv.c, qv[u].c)),
                                             __habs2(__hsub2(kv.d, qv[u].d)));
                        h_acc[i][u] = __hadd2(h_acc[i][u], __hadd2(s0, s1));
                    }
                }
            }
            #pragma unroll
            for (int i = 0; i < TI; i++)
                #pragma unroll
                for (int u = 0; u < NU; u++) {
                    float2 f2 = __half22float2(h_acc[i][u]);
                    f_acc[i][u] += f2.x + f2.y;
                }
        }

        // ---- Stores for tile n ----
        const int i0 = (ig0 + n) * TI;
        #pragma unroll
        for (int i = 0; i < TI; i++) {
            const size_t ob = (((size_t)b * S + (i0 + i)) * S + jbase) * H + h;
            #pragma unroll
            for (int u = 0; u < NU; u++)
                out[ob + (size_t)u * (32 * H)] = f_acc[i][u] * scale;
        }
        __syncthreads();   // all reads of kbuf[n&1] done before overwrite at n+1
    }
}

extern "C" void kernel_launch(void* const* d_in, const int* in_sizes, int n_in,
                              void* d_out, int out_size) {
    const float* q = (const float*)d_in[0];
    const float* k = (const float*)d_in[1];
    float* out     = (float*)d_out;

    cudaFuncSetAttribute(l1attn_kernel,
                         cudaFuncAttributeMaxDynamicSharedMemorySize, SMEM_BYTES);

    const int n4 = in_sizes[0] / 4;
    convert_kernel<<<(n4 + NT - 1) / NT, NT>>>(q, k, n4);

    const int B = in_sizes[0] / (S * H * D);  // = 8
    dim3 grid(S / JB, S / (TI * NI), B);
    l1attn_kernel<<<grid, NT, SMEM_BYTES>>>(out);
}